// round 9
// baseline (speedup 1.0000x reference)
#include <cuda_runtime.h>
#include <math.h>

// ---------------- problem constants (fixed by setup_inputs) ----------------
#define HDIM 28
#define NTOK 21952          // 28^3
#define C_ 256
#define NR 343              // 7^3 (SR-conv output tokens)
#define H2_ 4               // heads per branch
#define SCALE_F 0.17677669529663687f   // 32^-0.5
#define KSR 16384           // 256*4*4*4 im2col K
#define KZ 16               // split-K chunks for SR conv
#define KCH (KSR/KZ)        // 1024
#define NP 768              // packed projection width: q1|q2|kv2|y

// ---------------- scratch (device globals; no allocation) ----------------
__device__ float g_p   [NTOK*NP];     // packed: [0,128)=q1 [128,256)=q2 [256,512)=kv2 [512,768)=y
__device__ float g_lepe[NTOK*C_];
__device__ float g_x1p [KZ*NR*C_];
__device__ float g_x1  [NR*C_];
__device__ float g_kv1 [NR*C_];
__device__ float g_o   [NTOK*C_];
__device__ float g_wp  [NP*C_];       // packed weights
__device__ float g_bp  [NP];          // packed bias

// ---------------- weight packing (q1|q2|kv2|lepe) ----------------
__global__ void pack_w(const float* __restrict__ q1w, const float* __restrict__ q2w,
                       const float* __restrict__ kv2w, const float* __restrict__ lepew,
                       const float* __restrict__ lepeb,
                       float* __restrict__ wp, float* __restrict__ bp) {
    int i = blockIdx.x * 256 + threadIdx.x;
    if (i < NP * C_) {
        int r = i >> 8, c = i & 255;
        float v;
        if (r < 128)      v = q1w[r * C_ + c];
        else if (r < 256) v = q2w[(r - 128) * C_ + c];
        else if (r < 512) v = kv2w[(r - 256) * C_ + c];
        else              v = lepew[(r - 512) * C_ + c];
        wp[i] = v;
    }
    if (i < NP) bp[i] = (i >= 512) ? lepeb[i - 512] : 0.f;
}

// ------------- 128x128x16 fp32 GEMM: out[M,Nc] = (A+A2)[M,K] @ W[Nc,K]^T + bias -------
// Nc must be a multiple of 128. M guarded.
__global__ void __launch_bounds__(256, 2)
gemm128(const float* __restrict__ A, const float* __restrict__ A2,
        const float* __restrict__ W, const float* __restrict__ bias,
        float* __restrict__ out, int M, int K, int Nc) {
    __shared__ float As[16][128];
    __shared__ float Ws[16][128];
    const int tid = threadIdx.x;
    const int tx = tid & 15, ty = tid >> 4;
    const int bm = blockIdx.y << 7, bn = blockIdx.x << 7;

    const int lr = tid >> 1;          // 0..127 tile row for loads
    const int lc = (tid & 1) << 3;    // 0 or 8

    const int am = bm + lr;
    const bool aval = am < M;
    const float* Ap  = A + (size_t)am * K + lc;
    const float* A2p = A2 ? A2 + (size_t)am * K + lc : nullptr;
    const float* Wp  = W + (size_t)(bn + lr) * K + lc;

    float4 a0 = make_float4(0.f,0.f,0.f,0.f), a1 = a0, w0, w1;
    if (aval) {
        a0 = *(const float4*)(Ap);
        a1 = *(const float4*)(Ap + 4);
        if (A2p) {
            float4 b = *(const float4*)(A2p);
            a0.x += b.x; a0.y += b.y; a0.z += b.z; a0.w += b.w;
            b = *(const float4*)(A2p + 4);
            a1.x += b.x; a1.y += b.y; a1.z += b.z; a1.w += b.w;
        }
    }
    w0 = *(const float4*)(Wp);
    w1 = *(const float4*)(Wp + 4);

    float acc[8][8];
#pragma unroll
    for (int i = 0; i < 8; i++)
#pragma unroll
        for (int j = 0; j < 8; j++) acc[i][j] = 0.f;

    for (int k0 = 0; k0 < K; k0 += 16) {
        As[lc+0][lr]=a0.x; As[lc+1][lr]=a0.y; As[lc+2][lr]=a0.z; As[lc+3][lr]=a0.w;
        As[lc+4][lr]=a1.x; As[lc+5][lr]=a1.y; As[lc+6][lr]=a1.z; As[lc+7][lr]=a1.w;
        Ws[lc+0][lr]=w0.x; Ws[lc+1][lr]=w0.y; Ws[lc+2][lr]=w0.z; Ws[lc+3][lr]=w0.w;
        Ws[lc+4][lr]=w1.x; Ws[lc+5][lr]=w1.y; Ws[lc+6][lr]=w1.z; Ws[lc+7][lr]=w1.w;
        __syncthreads();

        const int kn = k0 + 16;
        if (kn < K) {
            a0 = make_float4(0.f,0.f,0.f,0.f); a1 = a0;
            if (aval) {
                a0 = *(const float4*)(Ap + kn);
                a1 = *(const float4*)(Ap + kn + 4);
                if (A2p) {
                    float4 b = *(const float4*)(A2p + kn);
                    a0.x += b.x; a0.y += b.y; a0.z += b.z; a0.w += b.w;
                    b = *(const float4*)(A2p + kn + 4);
                    a1.x += b.x; a1.y += b.y; a1.z += b.z; a1.w += b.w;
                }
            }
            w0 = *(const float4*)(Wp + kn);
            w1 = *(const float4*)(Wp + kn + 4);
        }

#pragma unroll
        for (int k = 0; k < 16; k++) {
            float4 x0 = *(const float4*)&As[k][ty << 3];
            float4 x1 = *(const float4*)&As[k][(ty << 3) + 4];
            float4 y0 = *(const float4*)&Ws[k][tx << 3];
            float4 y1 = *(const float4*)&Ws[k][(tx << 3) + 4];
            float av[8] = {x0.x,x0.y,x0.z,x0.w,x1.x,x1.y,x1.z,x1.w};
            float wv[8] = {y0.x,y0.y,y0.z,y0.w,y1.x,y1.y,y1.z,y1.w};
#pragma unroll
            for (int i = 0; i < 8; i++)
#pragma unroll
                for (int j = 0; j < 8; j++) acc[i][j] += av[i] * wv[j];
        }
        __syncthreads();
    }

    const int c0 = bn + (tx << 3);
    float b0[8];
#pragma unroll
    for (int j = 0; j < 8; j++) b0[j] = bias ? bias[c0 + j] : 0.f;
#pragma unroll
    for (int i = 0; i < 8; i++) {
        int r = bm + (ty << 3) + i;
        if (r < M) {
            float* op = out + (size_t)r * Nc + c0;
            float4 o0 = make_float4(acc[i][0]+b0[0], acc[i][1]+b0[1],
                                    acc[i][2]+b0[2], acc[i][3]+b0[3]);
            float4 o1 = make_float4(acc[i][4]+b0[4], acc[i][5]+b0[5],
                                    acc[i][6]+b0[6], acc[i][7]+b0[7]);
            *(float4*)op = o0;
            *(float4*)(op + 4) = o1;
        }
    }
}

// ---------------- depthwise 3x3x3 SAME conv; input = packed y (stride NP, off 512) ----
__global__ void dwconv3(const float* __restrict__ p, const float* __restrict__ w,
                        const float* __restrict__ b, float* __restrict__ out) {
    const int n = blockIdx.x;
    const int c = threadIdx.x;
    const int d  = n % HDIM;
    const int wv = (n / HDIM) % HDIM;
    const int h  = n / (HDIM * HDIM);

    float wreg[27];
#pragma unroll
    for (int j = 0; j < 27; j++) wreg[j] = w[c * 27 + j];

    float s = b[c];
#pragma unroll
    for (int kh = 0; kh < 3; kh++) {
        int hh = h + kh - 1;
        if (hh < 0 || hh >= HDIM) continue;
#pragma unroll
        for (int kw = 0; kw < 3; kw++) {
            int ww = wv + kw - 1;
            if (ww < 0 || ww >= HDIM) continue;
#pragma unroll
            for (int kd = 0; kd < 3; kd++) {
                int dd = d + kd - 1;
                if (dd < 0 || dd >= HDIM) continue;
                s += wreg[kh * 9 + kw * 3 + kd] *
                     p[(size_t)((hh * HDIM + ww) * HDIM + dd) * NP + 512 + c];
            }
        }
    }
    out[(size_t)n * C_ + c] = s;
}

// ---------------- SR conv as split-K im2col GEMM (partials, deterministic) ------------
__global__ void srconv_part(const float* __restrict__ x, const float* __restrict__ w,
                            float* __restrict__ part) {
    __shared__ float As[16][68];
    __shared__ float Ws[16][68];
    const int tid = threadIdx.x;
    const int tx = tid & 15, ty = tid >> 4;
    const int bn = blockIdx.x << 6;   // cout tile
    const int bm = blockIdx.y << 6;   // nr tile
    const int kz = blockIdx.z;        // K chunk
    const int arow = tid >> 2, ac = (tid & 3) << 2;

    const int nr = bm + arow;
    const bool aval = nr < NR;
    int oh = 0, ow = 0, od = 0;
    if (aval) { oh = nr / 49; int r = nr % 49; ow = r / 7; od = r % 7; }

    float acc[4][4];
#pragma unroll
    for (int i = 0; i < 4; i++)
#pragma unroll
        for (int j = 0; j < 4; j++) acc[i][j] = 0.f;

    const float* Wp = w + (size_t)(bn + arow) * KSR + kz * KCH;
    const int kbase = kz * KCH;

    for (int k0 = 0; k0 < KCH; k0 += 16) {
        const int kk = kbase + k0 + ac;      // multiple of 4 -> kd=0
        const int cin = kk >> 6;
        const int pbits = kk & 63;
        const int kh = pbits >> 4, kw = (pbits >> 2) & 3;
        float a0 = 0.f, a1 = 0.f, a2 = 0.f, a3 = 0.f;
        if (aval) {
            int nin0 = ((4 * oh + kh) * HDIM + 4 * ow + kw) * HDIM + 4 * od;
            const float* xp = x + (size_t)nin0 * C_ + cin;
            a0 = xp[0]; a1 = xp[C_]; a2 = xp[2 * C_]; a3 = xp[3 * C_];
        }
        As[ac + 0][arow] = a0; As[ac + 1][arow] = a1;
        As[ac + 2][arow] = a2; As[ac + 3][arow] = a3;

        float4 w4 = *(const float4*)(Wp + k0 + ac);
        Ws[ac + 0][arow] = w4.x; Ws[ac + 1][arow] = w4.y;
        Ws[ac + 2][arow] = w4.z; Ws[ac + 3][arow] = w4.w;
        __syncthreads();

#pragma unroll
        for (int k = 0; k < 16; k++) {
            float4 av = *(const float4*)&As[k][ty << 2];
            float4 bv = *(const float4*)&Ws[k][tx << 2];
            float a[4] = {av.x, av.y, av.z, av.w};
            float b[4] = {bv.x, bv.y, bv.z, bv.w};
#pragma unroll
            for (int i = 0; i < 4; i++)
#pragma unroll
                for (int j = 0; j < 4; j++) acc[i][j] += a[i] * b[j];
        }
        __syncthreads();
    }

#pragma unroll
    for (int i = 0; i < 4; i++) {
        int r = bm + (ty << 2) + i;
        if (r < NR) {
#pragma unroll
            for (int j = 0; j < 4; j++) {
                int c = bn + (tx << 2) + j;
                part[(size_t)kz * (NR * C_) + (size_t)r * C_ + c] = acc[i][j];
            }
        }
    }
}

__global__ void sr_reduce(float* __restrict__ x1, const float* __restrict__ part) {
    int i = blockIdx.x * 256 + threadIdx.x;
    if (i < NR * C_) {
        float s = 0.f;
#pragma unroll
        for (int z = 0; z < KZ; z++) s += part[(size_t)z * (NR * C_) + i];
        x1[i] = s;
    }
}

// ---------------- layernorm (+sr bias) + exact GELU, in place ----------------
__global__ void ln_gelu(float* __restrict__ x1, const float* __restrict__ srb,
                        const float* __restrict__ g, const float* __restrict__ b) {
    __shared__ float red[256];
    const int r = blockIdx.x, c = threadIdx.x;
    float v = x1[(size_t)r * C_ + c] + srb[c];

    red[c] = v; __syncthreads();
    for (int s = 128; s > 0; s >>= 1) { if (c < s) red[c] += red[c + s]; __syncthreads(); }
    float mu = red[0] * (1.f / 256.f);
    __syncthreads();

    float dv = v - mu;
    red[c] = dv * dv; __syncthreads();
    for (int s = 128; s > 0; s >>= 1) { if (c < s) red[c] += red[c + s]; __syncthreads(); }
    float var = red[0] * (1.f / 256.f);

    float xn = dv * rsqrtf(var + 1e-5f) * g[c] + b[c];
    float out = 0.5f * xn * (1.f + erff(xn * 0.70710678118654752f));
    x1[(size_t)r * C_ + c] = out;
}

// ---------------- branch 1: global attention vs 343 reduced tokens ----------------
// q from packed buffer (stride NP, offset h*32); kv1 dense [NR,256]; no-max softmax.
#define CH1 176
__global__ void attn_global(const float* __restrict__ p, const float* __restrict__ kv1,
                            float* __restrict__ o) {
    __shared__ float4 sk[CH1][8];
    __shared__ float4 sv[CH1][8];
    const int h = blockIdx.y;
    const int n = blockIdx.x * 256 + threadIdx.x;
    const bool valid = n < NTOK;

    float q[32];
    if (valid) {
        const float4* qp = (const float4*)(p + (size_t)n * NP + h * 32);
#pragma unroll
        for (int i = 0; i < 8; i++) {
            float4 t = qp[i];
            q[4*i] = t.x * SCALE_F; q[4*i+1] = t.y * SCALE_F;
            q[4*i+2] = t.z * SCALE_F; q[4*i+3] = t.w * SCALE_F;
        }
    }

    float l = 0.f, acc[32];
#pragma unroll
    for (int i = 0; i < 32; i++) acc[i] = 0.f;

    for (int c0 = 0; c0 < NR; c0 += CH1) {
        const int cn = min(CH1, NR - c0);
        for (int idx = threadIdx.x; idx < cn * 8; idx += 256) {
            int m = idx >> 3, dq = idx & 7;
            sk[m][dq] = *(const float4*)(kv1 + (size_t)(c0 + m) * C_ + h * 32 + dq * 4);
            sv[m][dq] = *(const float4*)(kv1 + (size_t)(c0 + m) * C_ + 128 + h * 32 + dq * 4);
        }
        __syncthreads();
        if (valid) {
            for (int m = 0; m < cn; m++) {
                float s = 0.f;
#pragma unroll
                for (int i = 0; i < 8; i++) {
                    float4 kk = sk[m][i];
                    s += q[4*i] * kk.x + q[4*i+1] * kk.y
                       + q[4*i+2] * kk.z + q[4*i+3] * kk.w;
                }
                float pw = __expf(s);
                l += pw;
#pragma unroll
                for (int i = 0; i < 8; i++) {
                    float4 vv = sv[m][i];
                    acc[4*i]   += pw * vv.x;
                    acc[4*i+1] += pw * vv.y;
                    acc[4*i+2] += pw * vv.z;
                    acc[4*i+3] += pw * vv.w;
                }
            }
        }
        __syncthreads();
    }

    if (valid) {
        float inv = 1.f / l;
        float4* op = (float4*)(o + (size_t)n * C_ + h * 32);
#pragma unroll
        for (int i = 0; i < 8; i++)
            op[i] = make_float4(acc[4*i]*inv, acc[4*i+1]*inv,
                                acc[4*i+2]*inv, acc[4*i+3]*inv);
    }
}

// ---------------- branch 2: 7x7x7 windowed attention (packed q/kv) ----------------
__global__ void attn_window(const float* __restrict__ p, float* __restrict__ o) {
    __shared__ float4 sk[CH1][8];
    __shared__ float4 sv[CH1][8];
    const int h = blockIdx.y;
    const int w = blockIdx.x;                 // 0..63
    const int wh = w >> 4, ww = (w >> 2) & 3, wd = w & 3;
    const int t = threadIdx.x;
    const bool valid = t < NR;

    int n = 0;
    if (valid) {
        int ih = t / 49, r = t % 49, iw = r / 7, id = r % 7;
        n = ((wh * 7 + ih) * HDIM + ww * 7 + iw) * HDIM + wd * 7 + id;
    }

    float q[32];
    if (valid) {
        const float4* qp = (const float4*)(p + (size_t)n * NP + 128 + h * 32);
#pragma unroll
        for (int i = 0; i < 8; i++) {
            float4 tt = qp[i];
            q[4*i] = tt.x * SCALE_F; q[4*i+1] = tt.y * SCALE_F;
            q[4*i+2] = tt.z * SCALE_F; q[4*i+3] = tt.w * SCALE_F;
        }
    }

    float l = 0.f, acc[32];
#pragma unroll
    for (int i = 0; i < 32; i++) acc[i] = 0.f;

    for (int c0 = 0; c0 < NR; c0 += CH1) {
        const int cn = min(CH1, NR - c0);
        for (int idx = t; idx < cn * 8; idx += 352) {
            int m = idx >> 3, dq = idx & 7;
            int tm = c0 + m;
            int ih = tm / 49, r = tm % 49, iw = r / 7, id = r % 7;
            int nm = ((wh * 7 + ih) * HDIM + ww * 7 + iw) * HDIM + wd * 7 + id;
            sk[m][dq] = *(const float4*)(p + (size_t)nm * NP + 256 + h * 32 + dq * 4);
            sv[m][dq] = *(const float4*)(p + (size_t)nm * NP + 384 + h * 32 + dq * 4);
        }
        __syncthreads();
        if (valid) {
            for (int m = 0; m < cn; m++) {
                float s = 0.f;
#pragma unroll
                for (int i = 0; i < 8; i++) {
                    float4 kk = sk[m][i];
                    s += q[4*i] * kk.x + q[4*i+1] * kk.y
                       + q[4*i+2] * kk.z + q[4*i+3] * kk.w;
                }
                float pw = __expf(s);
                l += pw;
#pragma unroll
                for (int i = 0; i < 8; i++) {
                    float4 vv = sv[m][i];
                    acc[4*i]   += pw * vv.x;
                    acc[4*i+1] += pw * vv.y;
                    acc[4*i+2] += pw * vv.z;
                    acc[4*i+3] += pw * vv.w;
                }
            }
        }
        __syncthreads();
    }

    if (valid) {
        float inv = 1.f / l;
        float4* op = (float4*)(o + (size_t)n * C_ + 128 + h * 32);
#pragma unroll
        for (int i = 0; i < 8; i++)
            op[i] = make_float4(acc[4*i]*inv, acc[4*i+1]*inv,
                                acc[4*i+2]*inv, acc[4*i+3]*inv);
    }
}

// ---------------- launch ----------------
extern "C" void kernel_launch(void* const* d_in, const int* in_sizes, int n_in,
                              void* d_out, int out_size) {
    const float* x       = (const float*)d_in[0];
    const float* lepe_w  = (const float*)d_in[4];
    const float* lepe_b  = (const float*)d_in[5];
    const float* lepe_cw = (const float*)d_in[6];
    const float* lepe_cb = (const float*)d_in[7];
    const float* sr_w    = (const float*)d_in[8];
    const float* sr_b    = (const float*)d_in[9];
    const float* norm_g  = (const float*)d_in[10];
    const float* norm_b  = (const float*)d_in[11];
    const float* q1_w    = (const float*)d_in[12];
    const float* kv1_w   = (const float*)d_in[13];
    const float* q2_w    = (const float*)d_in[14];
    const float* kv2_w   = (const float*)d_in[15];
    const float* proj_w  = (const float*)d_in[16];
    const float* proj_b  = (const float*)d_in[17];
    float* out = (float*)d_out;

    float *p, *lepe, *x1p, *x1, *kv1, *o, *wp, *bp;
    cudaGetSymbolAddress((void**)&p,    g_p);
    cudaGetSymbolAddress((void**)&lepe, g_lepe);
    cudaGetSymbolAddress((void**)&x1p,  g_x1p);
    cudaGetSymbolAddress((void**)&x1,   g_x1);
    cudaGetSymbolAddress((void**)&kv1,  g_kv1);
    cudaGetSymbolAddress((void**)&o,    g_o);
    cudaGetSymbolAddress((void**)&wp,   g_wp);
    cudaGetSymbolAddress((void**)&bp,   g_bp);

    const int MT = (NTOK + 127) / 128;   // 172 row tiles

    // Pack projection weights, then one fused GEMM: [q1|q2|kv2|y] = x @ Wp^T + bp
    pack_w<<<(NP * C_ + 255) / 256, 256>>>(q1_w, q2_w, kv2_w, lepe_w, lepe_b, wp, bp);
    gemm128<<<dim3(NP / 128, MT), 256>>>(x, nullptr, wp, bp, p, NTOK, C_, NP);

    // LePE depthwise conv from packed y
    dwconv3<<<NTOK, C_>>>(p, lepe_cw, lepe_cb, lepe);

    // SR conv -> LN -> GELU -> kv1
    srconv_part<<<dim3(C_ / 64, (NR + 63) / 64, KZ), 256>>>(x, sr_w, x1p);
    sr_reduce<<<(NR * C_ + 255) / 256, 256>>>(x1, x1p);
    ln_gelu<<<NR, C_>>>(x1, sr_b, norm_g, norm_b);
    gemm128<<<dim3(C_ / 128, (NR + 127) / 128), 256>>>(x1, nullptr, kv1_w, nullptr, kv1, NR, C_, C_);

    // Attention branches -> g_o (cols 0..127 branch1, 128..255 branch2)
    attn_global<<<dim3((NTOK + 255) / 256, H2_), 256>>>(p, kv1, o);
    attn_window<<<dim3(64, H2_), 352>>>(p, o);

    // Final projection with fused (+lepe)
    gemm128<<<dim3(C_ / 128, MT), 256>>>(o, lepe, proj_w, proj_b, out, NTOK, C_, C_);
}

// round 11
// speedup vs baseline: 1.0989x; 1.0989x over previous
#include <cuda_runtime.h>
#include <math.h>

// ---------------- problem constants (fixed by setup_inputs) ----------------
#define HDIM 28
#define NTOK 21952          // 28^3
#define C_ 256
#define NR 343              // 7^3 (SR-conv output tokens)
#define H2_ 4               // heads per branch
#define SCALE_F 0.17677669529663687f   // 32^-0.5
#define KSR 16384           // 256*4*4*4 im2col K
#define KZ 64               // split-K chunks for SR conv: one per kernel position
#define NP 768              // packed projection width: q1|q2|kv2|y

// ---------------- scratch (device globals; no allocation) ----------------
__device__ float g_p   [NTOK*NP];     // packed: [0,128)=q1 [128,256)=q2 [256,512)=kv2 [512,768)=y
__device__ float g_lepe[NTOK*C_];
__device__ float g_x1p [KZ*NR*C_];    // split-K partials (22.5 MB)
__device__ float g_x1  [NR*C_];
__device__ float g_kv1 [NR*C_];
__device__ float g_o   [NTOK*C_];
__device__ float g_wp  [NP*C_];       // packed projection weights
__device__ float g_bp  [NP];          // packed bias
__device__ float g_wsr [C_*KSR];      // sr_w transposed: [cout][kpos][cin]

// ---------------- weight packing (q1|q2|kv2|lepe) ----------------
__global__ void pack_w(const float* __restrict__ q1w, const float* __restrict__ q2w,
                       const float* __restrict__ kv2w, const float* __restrict__ lepew,
                       const float* __restrict__ lepeb,
                       float* __restrict__ wp, float* __restrict__ bp) {
    int i = blockIdx.x * 256 + threadIdx.x;
    if (i < NP * C_) {
        int r = i >> 8, c = i & 255;
        float v;
        if (r < 128)      v = q1w[r * C_ + c];
        else if (r < 256) v = q2w[(r - 128) * C_ + c];
        else if (r < 512) v = kv2w[(r - 256) * C_ + c];
        else              v = lepew[(r - 512) * C_ + c];
        wp[i] = v;
    }
    if (i < NP) bp[i] = (i >= 512) ? lepeb[i - 512] : 0.f;
}

// -------- sr weight transpose: w[cout][cin][kpos] -> wsr[cout][kpos][cin] --------
__global__ void pack_wsr(const float* __restrict__ w, float* __restrict__ wsr) {
    __shared__ float t[32][257];
    const int cout = blockIdx.x;          // 256 blocks
    const int tid = threadIdx.x;          // 256 threads = cin
    const float* wr = w + (size_t)cout * KSR + (size_t)tid * 64;
    float* wo = wsr + (size_t)cout * KSR;
#pragma unroll
    for (int half = 0; half < 2; half++) {
#pragma unroll
        for (int j4 = 0; j4 < 8; j4++) {
            float4 v = *(const float4*)(wr + half * 32 + j4 * 4);
            t[j4*4+0][tid] = v.x; t[j4*4+1][tid] = v.y;
            t[j4*4+2][tid] = v.z; t[j4*4+3][tid] = v.w;
        }
        __syncthreads();
#pragma unroll
        for (int j = 0; j < 32; j++)
            wo[(size_t)(half * 32 + j) * C_ + tid] = t[j][tid];
        __syncthreads();
    }
}

// ------------- 128x128x16 fp32 GEMM: out[M,Nc] = (A+A2)[M,K] @ W[Nc,K]^T + bias -------
// Nc must be a multiple of 128. M guarded.
__global__ void __launch_bounds__(256, 2)
gemm128(const float* __restrict__ A, const float* __restrict__ A2,
        const float* __restrict__ W, const float* __restrict__ bias,
        float* __restrict__ out, int M, int K, int Nc) {
    __shared__ float As[16][128];
    __shared__ float Ws[16][128];
    const int tid = threadIdx.x;
    const int tx = tid & 15, ty = tid >> 4;
    const int bm = blockIdx.y << 7, bn = blockIdx.x << 7;

    const int lr = tid >> 1;          // 0..127 tile row for loads
    const int lc = (tid & 1) << 3;    // 0 or 8

    const int am = bm + lr;
    const bool aval = am < M;
    const float* Ap  = A + (size_t)am * K + lc;
    const float* A2p = A2 ? A2 + (size_t)am * K + lc : nullptr;
    const float* Wp  = W + (size_t)(bn + lr) * K + lc;

    float4 a0 = make_float4(0.f,0.f,0.f,0.f), a1 = a0, w0, w1;
    if (aval) {
        a0 = *(const float4*)(Ap);
        a1 = *(const float4*)(Ap + 4);
        if (A2p) {
            float4 b = *(const float4*)(A2p);
            a0.x += b.x; a0.y += b.y; a0.z += b.z; a0.w += b.w;
            b = *(const float4*)(A2p + 4);
            a1.x += b.x; a1.y += b.y; a1.z += b.z; a1.w += b.w;
        }
    }
    w0 = *(const float4*)(Wp);
    w1 = *(const float4*)(Wp + 4);

    float acc[8][8];
#pragma unroll
    for (int i = 0; i < 8; i++)
#pragma unroll
        for (int j = 0; j < 8; j++) acc[i][j] = 0.f;

    for (int k0 = 0; k0 < K; k0 += 16) {
        As[lc+0][lr]=a0.x; As[lc+1][lr]=a0.y; As[lc+2][lr]=a0.z; As[lc+3][lr]=a0.w;
        As[lc+4][lr]=a1.x; As[lc+5][lr]=a1.y; As[lc+6][lr]=a1.z; As[lc+7][lr]=a1.w;
        Ws[lc+0][lr]=w0.x; Ws[lc+1][lr]=w0.y; Ws[lc+2][lr]=w0.z; Ws[lc+3][lr]=w0.w;
        Ws[lc+4][lr]=w1.x; Ws[lc+5][lr]=w1.y; Ws[lc+6][lr]=w1.z; Ws[lc+7][lr]=w1.w;
        __syncthreads();

        const int kn = k0 + 16;
        if (kn < K) {
            a0 = make_float4(0.f,0.f,0.f,0.f); a1 = a0;
            if (aval) {
                a0 = *(const float4*)(Ap + kn);
                a1 = *(const float4*)(Ap + kn + 4);
                if (A2p) {
                    float4 b = *(const float4*)(A2p + kn);
                    a0.x += b.x; a0.y += b.y; a0.z += b.z; a0.w += b.w;
                    b = *(const float4*)(A2p + kn + 4);
                    a1.x += b.x; a1.y += b.y; a1.z += b.z; a1.w += b.w;
                }
            }
            w0 = *(const float4*)(Wp + kn);
            w1 = *(const float4*)(Wp + kn + 4);
        }

#pragma unroll
        for (int k = 0; k < 16; k++) {
            float4 x0 = *(const float4*)&As[k][ty << 3];
            float4 x1 = *(const float4*)&As[k][(ty << 3) + 4];
            float4 y0 = *(const float4*)&Ws[k][tx << 3];
            float4 y1 = *(const float4*)&Ws[k][(tx << 3) + 4];
            float av[8] = {x0.x,x0.y,x0.z,x0.w,x1.x,x1.y,x1.z,x1.w};
            float wv[8] = {y0.x,y0.y,y0.z,y0.w,y1.x,y1.y,y1.z,y1.w};
#pragma unroll
            for (int i = 0; i < 8; i++)
#pragma unroll
                for (int j = 0; j < 8; j++) acc[i][j] += av[i] * wv[j];
        }
        __syncthreads();
    }

    const int c0 = bn + (tx << 3);
    float b0[8];
#pragma unroll
    for (int j = 0; j < 8; j++) b0[j] = bias ? bias[c0 + j] : 0.f;
#pragma unroll
    for (int i = 0; i < 8; i++) {
        int r = bm + (ty << 3) + i;
        if (r < M) {
            float* op = out + (size_t)r * Nc + c0;
            float4 o0 = make_float4(acc[i][0]+b0[0], acc[i][1]+b0[1],
                                    acc[i][2]+b0[2], acc[i][3]+b0[3]);
            float4 o1 = make_float4(acc[i][4]+b0[4], acc[i][5]+b0[5],
                                    acc[i][6]+b0[6], acc[i][7]+b0[7]);
            *(float4*)op = o0;
            *(float4*)(op + 4) = o1;
        }
    }
}

// ---- SR conv split-K GEMM: one block-z per kernel position (kpos), A contiguous ----
// part[kz][nr][cout] += x[tok(nr,kz)][:] . wsr[cout][kz][:]
__global__ void __launch_bounds__(256, 2)
srconv_gemm(const float* __restrict__ x, const float* __restrict__ wsr,
            float* __restrict__ part) {
    __shared__ float As[16][128];
    __shared__ float Ws[16][128];
    const int tid = threadIdx.x;
    const int tx = tid & 15, ty = tid >> 4;
    const int bn = blockIdx.x << 7;   // cout tile (0,128)
    const int bm = blockIdx.y << 7;   // nr tile (0,128,256)
    const int kz = blockIdx.z;        // kernel position 0..63

    const int kh = kz >> 4, kw = (kz >> 2) & 3, kd = kz & 3;

    const int lr = tid >> 1;
    const int lc = (tid & 1) << 3;

    const int nr = bm + lr;
    const bool aval = nr < NR;
    int tok = 0;
    if (aval) {
        int oh = nr / 49; int r = nr % 49; int ow = r / 7; int od = r % 7;
        tok = ((4 * oh + kh) * HDIM + 4 * ow + kw) * HDIM + 4 * od + kd;
    }
    const float* Ap = x + (size_t)tok * C_ + lc;
    const float* Wp = wsr + (size_t)(bn + lr) * KSR + (size_t)kz * C_ + lc;

    float4 a0 = make_float4(0.f,0.f,0.f,0.f), a1 = a0, w0, w1;
    if (aval) { a0 = *(const float4*)(Ap); a1 = *(const float4*)(Ap + 4); }
    w0 = *(const float4*)(Wp);
    w1 = *(const float4*)(Wp + 4);

    float acc[8][8];
#pragma unroll
    for (int i = 0; i < 8; i++)
#pragma unroll
        for (int j = 0; j < 8; j++) acc[i][j] = 0.f;

    for (int k0 = 0; k0 < C_; k0 += 16) {
        As[lc+0][lr]=a0.x; As[lc+1][lr]=a0.y; As[lc+2][lr]=a0.z; As[lc+3][lr]=a0.w;
        As[lc+4][lr]=a1.x; As[lc+5][lr]=a1.y; As[lc+6][lr]=a1.z; As[lc+7][lr]=a1.w;
        Ws[lc+0][lr]=w0.x; Ws[lc+1][lr]=w0.y; Ws[lc+2][lr]=w0.z; Ws[lc+3][lr]=w0.w;
        Ws[lc+4][lr]=w1.x; Ws[lc+5][lr]=w1.y; Ws[lc+6][lr]=w1.z; Ws[lc+7][lr]=w1.w;
        __syncthreads();

        const int kn = k0 + 16;
        if (kn < C_) {
            a0 = make_float4(0.f,0.f,0.f,0.f); a1 = a0;
            if (aval) { a0 = *(const float4*)(Ap + kn); a1 = *(const float4*)(Ap + kn + 4); }
            w0 = *(const float4*)(Wp + kn);
            w1 = *(const float4*)(Wp + kn + 4);
        }

#pragma unroll
        for (int k = 0; k < 16; k++) {
            float4 x0 = *(const float4*)&As[k][ty << 3];
            float4 x1 = *(const float4*)&As[k][(ty << 3) + 4];
            float4 y0 = *(const float4*)&Ws[k][tx << 3];
            float4 y1 = *(const float4*)&Ws[k][(tx << 3) + 4];
            float av[8] = {x0.x,x0.y,x0.z,x0.w,x1.x,x1.y,x1.z,x1.w};
            float wv[8] = {y0.x,y0.y,y0.z,y0.w,y1.x,y1.y,y1.z,y1.w};
#pragma unroll
            for (int i = 0; i < 8; i++)
#pragma unroll
                for (int j = 0; j < 8; j++) acc[i][j] += av[i] * wv[j];
        }
        __syncthreads();
    }

    const int c0 = bn + (tx << 3);
    float* pz = part + (size_t)kz * (NR * C_);
#pragma unroll
    for (int i = 0; i < 8; i++) {
        int r = bm + (ty << 3) + i;
        if (r < NR) {
            float* op = pz + (size_t)r * C_ + c0;
            *(float4*)op = make_float4(acc[i][0], acc[i][1], acc[i][2], acc[i][3]);
            *(float4*)(op + 4) = make_float4(acc[i][4], acc[i][5], acc[i][6], acc[i][7]);
        }
    }
}

__global__ void sr_reduce(float* __restrict__ x1, const float* __restrict__ part) {
    int i4 = blockIdx.x * 256 + threadIdx.x;     // float4 index
    const int n4 = NR * C_ / 4;                  // 21952
    if (i4 < n4) {
        float4 s = make_float4(0.f, 0.f, 0.f, 0.f);
#pragma unroll
        for (int z = 0; z < KZ; z++) {
            float4 v = ((const float4*)part)[(size_t)z * n4 + i4];
            s.x += v.x; s.y += v.y; s.z += v.z; s.w += v.w;
        }
        ((float4*)x1)[i4] = s;
    }
}

// ---------------- depthwise 3x3x3 SAME conv; input = packed y (stride NP, off 512) ----
__global__ void dwconv3(const float* __restrict__ p, const float* __restrict__ w,
                        const float* __restrict__ b, float* __restrict__ out) {
    const int n = blockIdx.x;
    const int c = threadIdx.x;
    const int d  = n % HDIM;
    const int wv = (n / HDIM) % HDIM;
    const int h  = n / (HDIM * HDIM);

    float wreg[27];
#pragma unroll
    for (int j = 0; j < 27; j++) wreg[j] = w[c * 27 + j];

    float s = b[c];
#pragma unroll
    for (int kh = 0; kh < 3; kh++) {
        int hh = h + kh - 1;
        if (hh < 0 || hh >= HDIM) continue;
#pragma unroll
        for (int kw = 0; kw < 3; kw++) {
            int ww = wv + kw - 1;
            if (ww < 0 || ww >= HDIM) continue;
#pragma unroll
            for (int kd = 0; kd < 3; kd++) {
                int dd = d + kd - 1;
                if (dd < 0 || dd >= HDIM) continue;
                s += wreg[kh * 9 + kw * 3 + kd] *
                     p[(size_t)((hh * HDIM + ww) * HDIM + dd) * NP + 512 + c];
            }
        }
    }
    out[(size_t)n * C_ + c] = s;
}

// ---------------- layernorm (+sr bias) + exact GELU, in place ----------------
__global__ void ln_gelu(float* __restrict__ x1, const float* __restrict__ srb,
                        const float* __restrict__ g, const float* __restrict__ b) {
    __shared__ float red[256];
    const int r = blockIdx.x, c = threadIdx.x;
    float v = x1[(size_t)r * C_ + c] + srb[c];

    red[c] = v; __syncthreads();
    for (int s = 128; s > 0; s >>= 1) { if (c < s) red[c] += red[c + s]; __syncthreads(); }
    float mu = red[0] * (1.f / 256.f);
    __syncthreads();

    float dv = v - mu;
    red[c] = dv * dv; __syncthreads();
    for (int s = 128; s > 0; s >>= 1) { if (c < s) red[c] += red[c + s]; __syncthreads(); }
    float var = red[0] * (1.f / 256.f);

    float xn = dv * rsqrtf(var + 1e-5f) * g[c] + b[c];
    float out = 0.5f * xn * (1.f + erff(xn * 0.70710678118654752f));
    x1[(size_t)r * C_ + c] = out;
}

// ---------------- branch 1: global attention vs 343 reduced tokens ----------------
#define CH1 176
__global__ void attn_global(const float* __restrict__ p, const float* __restrict__ kv1,
                            float* __restrict__ o) {
    __shared__ float4 sk[CH1][8];
    __shared__ float4 sv[CH1][8];
    const int h = blockIdx.y;
    const int n = blockIdx.x * 256 + threadIdx.x;
    const bool valid = n < NTOK;

    float q[32];
    if (valid) {
        const float4* qp = (const float4*)(p + (size_t)n * NP + h * 32);
#pragma unroll
        for (int i = 0; i < 8; i++) {
            float4 t = qp[i];
            q[4*i] = t.x * SCALE_F; q[4*i+1] = t.y * SCALE_F;
            q[4*i+2] = t.z * SCALE_F; q[4*i+3] = t.w * SCALE_F;
        }
    }

    float l = 0.f, acc[32];
#pragma unroll
    for (int i = 0; i < 32; i++) acc[i] = 0.f;

    for (int c0 = 0; c0 < NR; c0 += CH1) {
        const int cn = min(CH1, NR - c0);
        for (int idx = threadIdx.x; idx < cn * 8; idx += 256) {
            int m = idx >> 3, dq = idx & 7;
            sk[m][dq] = *(const float4*)(kv1 + (size_t)(c0 + m) * C_ + h * 32 + dq * 4);
            sv[m][dq] = *(const float4*)(kv1 + (size_t)(c0 + m) * C_ + 128 + h * 32 + dq * 4);
        }
        __syncthreads();
        if (valid) {
            for (int m = 0; m < cn; m++) {
                float s = 0.f;
#pragma unroll
                for (int i = 0; i < 8; i++) {
                    float4 kk = sk[m][i];
                    s += q[4*i] * kk.x + q[4*i+1] * kk.y
                       + q[4*i+2] * kk.z + q[4*i+3] * kk.w;
                }
                float pw = __expf(s);
                l += pw;
#pragma unroll
                for (int i = 0; i < 8; i++) {
                    float4 vv = sv[m][i];
                    acc[4*i]   += pw * vv.x;
                    acc[4*i+1] += pw * vv.y;
                    acc[4*i+2] += pw * vv.z;
                    acc[4*i+3] += pw * vv.w;
                }
            }
        }
        __syncthreads();
    }

    if (valid) {
        float inv = 1.f / l;
        float4* op = (float4*)(o + (size_t)n * C_ + h * 32);
#pragma unroll
        for (int i = 0; i < 8; i++)
            op[i] = make_float4(acc[4*i]*inv, acc[4*i+1]*inv,
                                acc[4*i+2]*inv, acc[4*i+3]*inv);
    }
}

// ---------------- branch 2: 7x7x7 windowed attention (packed q/kv) ----------------
__global__ void attn_window(const float* __restrict__ p, float* __restrict__ o) {
    __shared__ float4 sk[CH1][8];
    __shared__ float4 sv[CH1][8];
    const int h = blockIdx.y;
    const int w = blockIdx.x;                 // 0..63
    const int wh = w >> 4, ww = (w >> 2) & 3, wd = w & 3;
    const int t = threadIdx.x;
    const bool valid = t < NR;

    int n = 0;
    if (valid) {
        int ih = t / 49, r = t % 49, iw = r / 7, id = r % 7;
        n = ((wh * 7 + ih) * HDIM + ww * 7 + iw) * HDIM + wd * 7 + id;
    }

    float q[32];
    if (valid) {
        const float4* qp = (const float4*)(p + (size_t)n * NP + 128 + h * 32);
#pragma unroll
        for (int i = 0; i < 8; i++) {
            float4 tt = qp[i];
            q[4*i] = tt.x * SCALE_F; q[4*i+1] = tt.y * SCALE_F;
            q[4*i+2] = tt.z * SCALE_F; q[4*i+3] = tt.w * SCALE_F;
        }
    }

    float l = 0.f, acc[32];
#pragma unroll
    for (int i = 0; i < 32; i++) acc[i] = 0.f;

    for (int c0 = 0; c0 < NR; c0 += CH1) {
        const int cn = min(CH1, NR - c0);
        for (int idx = t; idx < cn * 8; idx += 352) {
            int m = idx >> 3, dq = idx & 7;
            int tm = c0 + m;
            int ih = tm / 49, r = tm % 49, iw = r / 7, id = r % 7;
            int nm = ((wh * 7 + ih) * HDIM + ww * 7 + iw) * HDIM + wd * 7 + id;
            sk[m][dq] = *(const float4*)(p + (size_t)nm * NP + 256 + h * 32 + dq * 4);
            sv[m][dq] = *(const float4*)(p + (size_t)nm * NP + 384 + h * 32 + dq * 4);
        }
        __syncthreads();
        if (valid) {
            for (int m = 0; m < cn; m++) {
                float s = 0.f;
#pragma unroll
                for (int i = 0; i < 8; i++) {
                    float4 kk = sk[m][i];
                    s += q[4*i] * kk.x + q[4*i+1] * kk.y
                       + q[4*i+2] * kk.z + q[4*i+3] * kk.w;
                }
                float pw = __expf(s);
                l += pw;
#pragma unroll
                for (int i = 0; i < 8; i++) {
                    float4 vv = sv[m][i];
                    acc[4*i]   += pw * vv.x;
                    acc[4*i+1] += pw * vv.y;
                    acc[4*i+2] += pw * vv.z;
                    acc[4*i+3] += pw * vv.w;
                }
            }
        }
        __syncthreads();
    }

    if (valid) {
        float inv = 1.f / l;
        float4* op = (float4*)(o + (size_t)n * C_ + 128 + h * 32);
#pragma unroll
        for (int i = 0; i < 8; i++)
            op[i] = make_float4(acc[4*i]*inv, acc[4*i+1]*inv,
                                acc[4*i+2]*inv, acc[4*i+3]*inv);
    }
}

// ---------------- launch ----------------
extern "C" void kernel_launch(void* const* d_in, const int* in_sizes, int n_in,
                              void* d_out, int out_size) {
    const float* x       = (const float*)d_in[0];
    const float* lepe_w  = (const float*)d_in[4];
    const float* lepe_b  = (const float*)d_in[5];
    const float* lepe_cw = (const float*)d_in[6];
    const float* lepe_cb = (const float*)d_in[7];
    const float* sr_w    = (const float*)d_in[8];
    const float* sr_b    = (const float*)d_in[9];
    const float* norm_g  = (const float*)d_in[10];
    const float* norm_b  = (const float*)d_in[11];
    const float* q1_w    = (const float*)d_in[12];
    const float* kv1_w   = (const float*)d_in[13];
    const float* q2_w    = (const float*)d_in[14];
    const float* kv2_w   = (const float*)d_in[15];
    const float* proj_w  = (const float*)d_in[16];
    const float* proj_b  = (const float*)d_in[17];
    float* out = (float*)d_out;

    float *p, *lepe, *x1p, *x1, *kv1, *o, *wp, *bp, *wsr;
    cudaGetSymbolAddress((void**)&p,    g_p);
    cudaGetSymbolAddress((void**)&lepe, g_lepe);
    cudaGetSymbolAddress((void**)&x1p,  g_x1p);
    cudaGetSymbolAddress((void**)&x1,   g_x1);
    cudaGetSymbolAddress((void**)&kv1,  g_kv1);
    cudaGetSymbolAddress((void**)&o,    g_o);
    cudaGetSymbolAddress((void**)&wp,   g_wp);
    cudaGetSymbolAddress((void**)&bp,   g_bp);
    cudaGetSymbolAddress((void**)&wsr,  g_wsr);

    const int MT = (NTOK + 127) / 128;   // 172 row tiles

    // Pack projection weights, then one fused GEMM: [q1|q2|kv2|y] = x @ Wp^T + bp
    pack_w<<<(NP * C_ + 255) / 256, 256>>>(q1_w, q2_w, kv2_w, lepe_w, lepe_b, wp, bp);
    gemm128<<<dim3(NP / 128, MT), 256>>>(x, nullptr, wp, bp, p, NTOK, C_, NP);

    // LePE depthwise conv from packed y
    dwconv3<<<NTOK, C_>>>(p, lepe_cw, lepe_cb, lepe);

    // SR conv: transpose weights, 64-way split-K contiguous GEMM, reduce, LN+GELU, kv1
    pack_wsr<<<C_, 256>>>(sr_w, wsr);
    srconv_gemm<<<dim3(C_ / 128, (NR + 127) / 128, KZ), 256>>>(x, wsr, x1p);
    sr_reduce<<<(NR * C_ / 4 + 255) / 256, 256>>>(x1, x1p);
    ln_gelu<<<NR, C_>>>(x1, sr_b, norm_g, norm_b);
    gemm128<<<dim3(C_ / 128, (NR + 127) / 128), 256>>>(x1, nullptr, kv1_w, nullptr, kv1, NR, C_, C_);

    // Attention branches -> g_o (cols 0..127 branch1, 128..255 branch2)
    attn_global<<<dim3((NTOK + 255) / 256, H2_), 256>>>(p, kv1, o);
    attn_window<<<dim3(64, H2_), 352>>>(p, o);

    // Final projection with fused (+lepe)
    gemm128<<<dim3(C_ / 128, MT), 256>>>(o, lepe, proj_w, proj_b, out, NTOK, C_, C_);
}